// round 1
// baseline (speedup 1.0000x reference)
#include <cuda_runtime.h>
#include <cstdint>

// Problem constants (from reference)
#define T 4
#define E 250000
#define D 128
#define B 4096
#define L 50

// One warp per bag (t, b). Lane ln owns float4 at column ln*4.
// weights: [T, E, D] fp32, indices: [T, B, L] int32, out: [B, T*D] fp32.
__global__ __launch_bounds__(256, 8)
void embbag_kernel(const float4* __restrict__ weights4,
                   const int*    __restrict__ indices,
                   float4*       __restrict__ out4) {
    const int warp_global = (blockIdx.x * blockDim.x + threadIdx.x) >> 5;
    const int lane = threadIdx.x & 31;
    if (warp_global >= T * B) return;

    const int t = warp_global / B;      // table-major: one table's working set per wave
    const int b = warp_global % B;

    const int* __restrict__ idx = indices + ((size_t)t * B + b) * L;
    const float4* __restrict__ wt = weights4 + (size_t)t * E * (D / 4);

    float4 acc = make_float4(0.f, 0.f, 0.f, 0.f);

    // L = 50 = 10 groups of 5: prefetch 5 indices, issue 5 independent LDG.128
    #pragma unroll 2
    for (int l = 0; l < L; l += 5) {
        const int i0 = __ldg(idx + l + 0);
        const int i1 = __ldg(idx + l + 1);
        const int i2 = __ldg(idx + l + 2);
        const int i3 = __ldg(idx + l + 3);
        const int i4 = __ldg(idx + l + 4);

        const float4 r0 = __ldg(wt + (size_t)i0 * (D / 4) + lane);
        const float4 r1 = __ldg(wt + (size_t)i1 * (D / 4) + lane);
        const float4 r2 = __ldg(wt + (size_t)i2 * (D / 4) + lane);
        const float4 r3 = __ldg(wt + (size_t)i3 * (D / 4) + lane);
        const float4 r4 = __ldg(wt + (size_t)i4 * (D / 4) + lane);

        acc.x += r0.x + r1.x + r2.x + r3.x + r4.x;
        acc.y += r0.y + r1.y + r2.y + r3.y + r4.y;
        acc.z += r0.z + r1.z + r2.z + r3.z + r4.z;
        acc.w += r0.w + r1.w + r2.w + r3.w + r4.w;
    }

    // out[b][t*D + lane*4 .. +3]
    out4[((size_t)b * T + t) * (D / 4) + lane] = acc;
}

extern "C" void kernel_launch(void* const* d_in, const int* in_sizes, int n_in,
                              void* d_out, int out_size) {
    const float4* weights4 = (const float4*)d_in[0];  // [T, E, D] fp32
    const int*    indices  = (const int*)d_in[1];     // [T, B, L] int32
    float4*       out4     = (float4*)d_out;          // [B, T*D] fp32

    const int total_warps = T * B;          // 16384 bags
    const int threads = 256;                // 8 warps / CTA
    const int blocks = (total_warps * 32 + threads - 1) / threads;  // 2048

    embbag_kernel<<<blocks, threads>>>(weights4, indices, out4);
}

// round 3
// speedup vs baseline: 1.0491x; 1.0491x over previous
#include <cuda_runtime.h>
#include <cstdint>

// Problem constants
#define T 4
#define E 250000
#define D 128
#define B 4096
#define L 50

// 256-bit weight-row gather with L2 evict_last (sm_103 requires v8 width for this hint).
// Loads 8 consecutive floats (32B) per lane.
__device__ __forceinline__ void ldg256_evict_last(const float* p, float* v) {
    asm("ld.global.nc.L2::evict_last.v8.f32 {%0,%1,%2,%3,%4,%5,%6,%7}, [%8];"
        : "=f"(v[0]), "=f"(v[1]), "=f"(v[2]), "=f"(v[3]),
          "=f"(v[4]), "=f"(v[5]), "=f"(v[6]), "=f"(v[7])
        : "l"(p));
}

// Streaming 128-bit store (write-once output; don't pollute L2).
__device__ __forceinline__ void stg_cs4(float* p, float a, float b, float c, float d) {
    asm volatile("st.global.cs.v4.f32 [%0], {%1,%2,%3,%4};"
                 :: "l"(p), "f"(a), "f"(b), "f"(c), "f"(d));
}

// One warp per bag (t, b). Each load step: lanes 0-15 fetch row idx[2s],
// lanes 16-31 fetch row idx[2s+1]; lane holds 8 floats (cols ln16*8 .. +7).
__global__ __launch_bounds__(256)
void embbag_kernel(const float* __restrict__ weights,
                   const int*   __restrict__ indices,
                   float*       __restrict__ out) {
    const int warp_global = (blockIdx.x * blockDim.x + threadIdx.x) >> 5;
    const int lane = threadIdx.x & 31;
    if (warp_global >= T * B) return;

    const int t = warp_global >> 12;        // / B (4096)
    const int b = warp_global & (B - 1);

    const int half = lane >> 4;             // 0: even rows, 1: odd rows
    const int ln16 = lane & 15;             // 32B chunk within row

    const int* __restrict__ idx = indices + ((size_t)t * B + b) * L;

    // Preload all 50 indices: 2 coalesced loads, distribute via shfl.
    const int ia = __ldg(idx + lane);                               // idx[0..31]
    const int ib = (lane < (L - 32)) ? __ldg(idx + 32 + lane) : 0;  // idx[32..49]

    const float* __restrict__ wt = weights + (size_t)t * E * D;

    float a0[8] = {0,0,0,0,0,0,0,0};
    float a1[8] = {0,0,0,0,0,0,0,0};

    // 25 row-pairs, in 5 batches of 5 independent LDG.256
    #pragma unroll
    for (int s0 = 0; s0 < 25; s0 += 5) {
        const float* p[5];
        #pragma unroll
        for (int k = 0; k < 5; k++) {
            const int s = s0 + k;
            const int sel = 2 * s + half;   // warp-uniform branch: 2s+1<32 <=> s<16
            const int j = (2 * s >= 32) ? __shfl_sync(0xffffffffu, ib, sel - 32)
                                        : __shfl_sync(0xffffffffu, ia, sel);
            p[k] = wt + (size_t)j * D + ln16 * 8;
        }
        float r[5][8];
        #pragma unroll
        for (int k = 0; k < 5; k++) ldg256_evict_last(p[k], r[k]);

        #pragma unroll
        for (int k = 0; k < 5; k++) {
            float* a = (k & 1) ? a1 : a0;   // two accumulation chains
            #pragma unroll
            for (int e = 0; e < 8; e++) a[e] += r[k][e];
        }
    }

    // Fold odd-row half-warp partials into lanes 0-15.
    float acc[8];
    #pragma unroll
    for (int e = 0; e < 8; e++) {
        float v = a0[e] + a1[e];
        v += __shfl_down_sync(0xffffffffu, v, 16);
        acc[e] = v;
    }

    // Lanes 0-15 write 32B each: out[b][t*D + ln16*8 .. +7]  (coalesced 512B)
    if (half == 0) {
        float* o = out + ((size_t)b * T + t) * D + ln16 * 8;
        stg_cs4(o,     acc[0], acc[1], acc[2], acc[3]);
        stg_cs4(o + 4, acc[4], acc[5], acc[6], acc[7]);
    }
}

extern "C" void kernel_launch(void* const* d_in, const int* in_sizes, int n_in,
                              void* d_out, int out_size) {
    const float* weights = (const float*)d_in[0];   // [T, E, D] fp32
    const int*   indices = (const int*)d_in[1];     // [T, B, L] int32
    float*       out     = (float*)d_out;           // [B, T*D] fp32

    const int total_warps = T * B;                   // 16384 bags
    const int threads = 256;                         // 8 warps / CTA
    const int blocks = (total_warps * 32) / threads; // 2048

    embbag_kernel<<<blocks, threads>>>(weights, indices, out);
}